// round 2
// baseline (speedup 1.0000x reference)
#include <cuda_runtime.h>

#define NN   50000
#define IN_F 256
#define AD   128
#define NH   8
#define DK   16
#define NE   1600000

// Scratch (no cudaMalloc allowed): q/k projections + per-(node,head) softmax sums
__device__ float g_q[(size_t)NN * AD];      // 25.6 MB
__device__ float g_k[(size_t)NN * AD];      // 25.6 MB
__device__ float g_sum[NN * NH];            // 1.6 MB

// ---------------------------------------------------------------------------
// Zero the softmax accumulator
// ---------------------------------------------------------------------------
__global__ void zero_kernel() {
    int i = blockIdx.x * blockDim.x + threadIdx.x;
    if (i < NN * NH) g_sum[i] = 0.0f;
}

// ---------------------------------------------------------------------------
// Projection GEMM: out[n, a] = sum_i hi[n,i] * W[a,i] + bias[a]
// Tile: M=64 nodes, N=128 outputs, K=32. 256 threads, 4x8 micro-tile/thread.
// which==0 -> g_q, which==1 -> g_k
// ---------------------------------------------------------------------------
__global__ void proj_kernel(const float* __restrict__ hi,
                            const float* __restrict__ W,
                            const float* __restrict__ bias,
                            int which) {
    float* out = which ? g_k : g_q;
    __shared__ float a_s[64 * 33];
    __shared__ float b_s[128 * 33];

    const int tid = threadIdx.x;
    const int m0  = blockIdx.x * 64;

    float acc[4][8];
#pragma unroll
    for (int i = 0; i < 4; i++)
#pragma unroll
        for (int j = 0; j < 8; j++) acc[i][j] = 0.0f;

    const float4* hi4 = (const float4*)hi;   // row stride 64 float4
    const float4* W4  = (const float4*)W;    // row stride 64 float4

    const int ar = tid >> 2, aq = tid & 3;   // A loader: row 0..63, quarter 0..3
    const int bo = tid >> 1, bq = tid & 1;   // B loader: out 0..127, half 0..1
    const int ty = tid >> 4, tx = tid & 15;  // compute mapping

    for (int kc = 0; kc < IN_F; kc += 32) {
        const int kc4 = kc >> 2;
        // Load A tile: 64 x 32, each thread 2 float4 (guarded rows -> 0)
#pragma unroll
        for (int j = 0; j < 2; j++) {
            float4 v = make_float4(0.f, 0.f, 0.f, 0.f);
            int row = m0 + ar;
            if (row < NN) v = hi4[(size_t)row * 64 + kc4 + aq * 2 + j];
            int c = (aq * 2 + j) * 4;
            a_s[ar * 33 + c + 0] = v.x;
            a_s[ar * 33 + c + 1] = v.y;
            a_s[ar * 33 + c + 2] = v.z;
            a_s[ar * 33 + c + 3] = v.w;
        }
        // Load B tile: 128 x 32, each thread 4 float4
#pragma unroll
        for (int j = 0; j < 4; j++) {
            float4 v = W4[(size_t)bo * 64 + kc4 + bq * 4 + j];
            int c = (bq * 4 + j) * 4;
            b_s[bo * 33 + c + 0] = v.x;
            b_s[bo * 33 + c + 1] = v.y;
            b_s[bo * 33 + c + 2] = v.z;
            b_s[bo * 33 + c + 3] = v.w;
        }
        __syncthreads();

#pragma unroll
        for (int kk = 0; kk < 32; kk++) {
            float arr[4], brr[8];
#pragma unroll
            for (int i = 0; i < 4; i++) arr[i] = a_s[(ty * 4 + i) * 33 + kk];
#pragma unroll
            for (int j = 0; j < 8; j++) brr[j] = b_s[(tx * 8 + j) * 33 + kk];
#pragma unroll
            for (int i = 0; i < 4; i++)
#pragma unroll
                for (int j = 0; j < 8; j++)
                    acc[i][j] = fmaf(arr[i], brr[j], acc[i][j]);
        }
        __syncthreads();
    }

#pragma unroll
    for (int i = 0; i < 4; i++) {
        int row = m0 + ty * 4 + i;
        if (row < NN) {
#pragma unroll
            for (int j = 0; j < 8; j++) {
                int col = tx * 8 + j;
                out[(size_t)row * AD + col] = acc[i][j] + bias[col];
            }
        }
    }
}

// ---------------------------------------------------------------------------
// Edge pass: one warp per edge (grid-stride).
// lane l owns features [4l, 4l+4). Head h = features [16h, 16h+16) = lanes 4h..4h+3.
// prods[e,h] = dot(q[src]+r*Qrw+Qrb, k[dst]) / 4 ; ex = exp(prods); atomicAdd sum.
// Head results are shuffled to lanes 0..7 so the 32B/edge output writes are
// contiguous (coalesced) instead of an 8x4B strided scatter.
// ---------------------------------------------------------------------------
__global__ void edge_kernel(const float* __restrict__ radial,
                            const int*  __restrict__ edge,
                            const float* __restrict__ Qrw,
                            const float* __restrict__ Qrb,
                            float* __restrict__ att,
                            float* __restrict__ prods) {
    const int lane = threadIdx.x & 31;
    const int gw = (blockIdx.x * blockDim.x + threadIdx.x) >> 5;
    const int nw = (gridDim.x * blockDim.x) >> 5;

    const float4 qrw4 = ((const float4*)Qrw)[lane];
    const float4 qrb4 = ((const float4*)Qrb)[lane];
    const int* e0 = edge;
    const int* e1 = edge + NE;
    const float4* q4p = (const float4*)g_q;
    const float4* k4p = (const float4*)g_k;

    for (int e = gw; e < NE; e += nw) {
        const int src = e0[e];
        const int dst = e1[e];
        const float r = radial[e];
        const float4 q4 = q4p[(size_t)src * 32 + lane];
        const float4 k4 = k4p[(size_t)dst * 32 + lane];

        float sx = q4.x + fmaf(r, qrw4.x, qrb4.x);
        float sy = q4.y + fmaf(r, qrw4.y, qrb4.y);
        float sz = q4.z + fmaf(r, qrw4.z, qrb4.z);
        float sw = q4.w + fmaf(r, qrw4.w, qrb4.w);

        float p = sx * k4.x;
        p = fmaf(sy, k4.y, p);
        p = fmaf(sz, k4.z, p);
        p = fmaf(sw, k4.w, p);
        // reduce over the 4 lanes of each head: lanes 4h..4h+3 -> lane 4h
        p += __shfl_xor_sync(0xffffffff, p, 1);
        p += __shfl_xor_sync(0xffffffff, p, 2);
        // gather head sums to lanes 0..7: lane l reads from lane (l&7)*4
        const float ph = __shfl_sync(0xffffffff, p, (lane & 7) << 2);

        if (lane < NH) {
            const float pr = ph * 0.25f;           // / sqrt(DK) = /4
            prods[(size_t)e * NH + lane] = pr;
            const float ex = __expf(pr);
            att[(size_t)e * NH + lane] = ex;
            atomicAdd(&g_sum[src * NH + lane], ex);
        }
    }
}

// ---------------------------------------------------------------------------
// Normalize: att[e,h] = ex / sum[src,h]
// ---------------------------------------------------------------------------
__global__ void norm_kernel(const int* __restrict__ edge,
                            float* __restrict__ att) {
    int i = blockIdx.x * blockDim.x + threadIdx.x;
    if (i < NE * NH) {
        int e = i >> 3;
        int h = i & 7;
        att[i] = att[i] / g_sum[edge[e] * NH + h];
    }
}

// ---------------------------------------------------------------------------
extern "C" void kernel_launch(void* const* d_in, const int* in_sizes, int n_in,
                              void* d_out, int out_size) {
    const float* hi     = (const float*)d_in[0];
    const float* radial = (const float*)d_in[1];
    const float* Qw     = (const float*)d_in[2];
    const float* Qb     = (const float*)d_in[3];
    const float* Qrw    = (const float*)d_in[4];
    const float* Qrb    = (const float*)d_in[5];
    const float* Kw     = (const float*)d_in[6];
    const float* Kb     = (const float*)d_in[7];
    const int*   edge   = (const int*)d_in[8];

    float* out   = (float*)d_out;
    float* att   = out;                       // [E, H]
    float* prods = out + (size_t)NE * NH;     // [E, H]

    zero_kernel<<<(NN * NH + 255) / 256, 256>>>();
    proj_kernel<<<(NN + 63) / 64, 256>>>(hi, Qw, Qb, 0);
    proj_kernel<<<(NN + 63) / 64, 256>>>(hi, Kw, Kb, 1);
    edge_kernel<<<2048, 256>>>(radial, edge, Qrw, Qrb, att, prods);
    norm_kernel<<<(NE * NH + 255) / 256, 256>>>(edge, att);
}